// round 15
// baseline (speedup 1.0000x reference)
#include <cuda_runtime.h>
#include <math.h>
#include <stdint.h>

// Problem constants
#define B_   4
#define N_   8400
#define NM_  32
#define H_   160
#define W_   160
#define D_   100
#define HW_  (H_*W_)          // 25600
#define OW_  640
#define OH_  640

// Scratch: sigmoid masks [B][D][H][W] fp32 = 40.96 MB
__device__ float g_S[(size_t)B_ * D_ * HW_];

// Packed fp32x2 FMA (Blackwell FFMA2) — PTX-only
__device__ __forceinline__ float2 ffma2(float2 a, float2 b, float2 c) {
    union { float2 f; unsigned long long u; } ua, ub, uc, ur;
    ua.f = a; ub.f = b; uc.f = c;
    asm("fma.rn.f32x2 %0, %1, %2, %3;" : "=l"(ur.u) : "l"(ua.u), "l"(ub.u), "l"(uc.u));
    return ur.f;
}

// ---------------------------------------------------------------------------
// Kernel A (R8 design — best measured, 28.4us full / ~16us per half):
// coeff gather + GEMM over NM=32 + sigmoid -> g_S.
// Per d-half launch: grid (25, 5, 4); block 256; 3 CTAs/SM.
// Thread: 4 adjacent px x 10 d via FFMA2.
// ---------------------------------------------------------------------------
#define DT_  10
#define PXT_ 4

__global__ void __launch_bounds__(256, 3)
kernelA(const float* __restrict__ mc,
        const float* __restrict__ proto,
        const void* __restrict__ det,      // int32 vs int64 detected on device
        const int dBase)
{
    const int b  = blockIdx.z;
    const int d0 = dBase + blockIdx.y * DT_;
    const int p0 = blockIdx.x * (256 * PXT_) + threadIdx.x * PXT_;

    // int64 det values < 2^31 -> all odd int32 words zero
    const int* d32 = (const int*)det;
    bool is64 = true;
    #pragma unroll
    for (int k = 0; k < 8; k++) if (d32[2 * k + 1] != 0) is64 = false;

    __shared__ float sc[NM_][DT_];
    for (int i = threadIdx.x; i < NM_ * DT_; i += 256) {
        const int n = i / DT_;
        const int d = i % DT_;
        const int flat = b * D_ + d0 + d;
        long long idx = is64 ? ((const long long*)det)[flat] : (long long)d32[flat];
        idx = min(max(idx, 0LL), (long long)(N_ - 1));
        sc[n][d] = mc[((long long)b * N_ + idx) * NM_ + n];
    }
    __syncthreads();

    float2 acc[DT_][2];
    #pragma unroll
    for (int d = 0; d < DT_; d++) {
        acc[d][0] = make_float2(0.f, 0.f);
        acc[d][1] = make_float2(0.f, 0.f);
    }

    const float* pbase = proto + (size_t)b * NM_ * HW_ + p0;

    #pragma unroll 8
    for (int n = 0; n < NM_; n++) {
        const float4 p = *reinterpret_cast<const float4*>(pbase + (size_t)n * HW_);
        const float2 pa = make_float2(p.x, p.y);
        const float2 pb = make_float2(p.z, p.w);
        #pragma unroll
        for (int d = 0; d < DT_; d++) {
            const float c = sc[n][d];
            const float2 cc = make_float2(c, c);
            acc[d][0] = ffma2(pa, cc, acc[d][0]);
            acc[d][1] = ffma2(pb, cc, acc[d][1]);
        }
    }

    #pragma unroll
    for (int d = 0; d < DT_; d++) {
        float4 s;
        s.x = 1.0f / (1.0f + expf(-acc[d][0].x));
        s.y = 1.0f / (1.0f + expf(-acc[d][0].y));
        s.z = 1.0f / (1.0f + expf(-acc[d][1].x));
        s.w = 1.0f / (1.0f + expf(-acc[d][1].y));
        *reinterpret_cast<float4*>(g_S + ((size_t)(b * D_ + d0 + d)) * HW_ + p0) = s;
    }
}

// ---------------------------------------------------------------------------
// Kernel B (R9/R14 design — best measured, 104.8us aggregate): 4x bilinear
// upsample + threshold; per-warp row pipelines, per-row TMA bulk stores
// (double-buffered, wait_group.read 1).
// Per d-half launch: grid (8 bands, 50 d, 4 b); block 256; smem 55 KB.
// ---------------------------------------------------------------------------
#define SRCROWS      22                                  // 20 + 2 halo
#define BAND_FLOATS  (SRCROWS * 160)                     // 3520 floats
#define ROW_FLOATS   OW_                                 // 640 floats = 2560 B
#define SMEMB_BYTES  ((BAND_FLOATS + 8 * 2 * ROW_FLOATS) * 4)   // 55040 B

__global__ void __launch_bounds__(256)
kernelB(float* __restrict__ out, const int dBase)
{
    extern __shared__ float smem[];
    float* sS = smem;                                    // [22][160] band

    const int band = blockIdx.x;                         // 0..7
    const int d    = dBase + blockIdx.y;
    const int b    = blockIdx.z;
    const int R0   = 20 * band - 1;                      // first band source row
    const int Y0   = 80 * band;

    // load source band (smem row r holds global row clamp(R0 + r))
    const float* Sg = g_S + ((size_t)(b * D_ + d)) * HW_;
    for (int i = threadIdx.x; i < SRCROWS * 40; i += 256) {
        const int r  = i / 40;
        const int x4 = i % 40;
        const int gr = min(max(R0 + r, 0), H_ - 1);
        *reinterpret_cast<float4*>(&sS[r * 160 + x4 * 4]) =
            *reinterpret_cast<const float4*>(Sg + gr * 160 + x4 * 4);
    }
    __syncthreads();

    const int w    = threadIdx.x >> 5;
    const int lane = threadIdx.x & 31;
    float* wstage = smem + BAND_FLOATS + w * (2 * ROW_FLOATS);
    const char* gbase = (const char*)(out + ((size_t)(b * D_ + d)) * (OH_ * OW_));

    for (int ri = 0; ri < 10; ri++) {
        const int y   = Y0 + w + 8 * ri;
        const int buf = ri & 1;
        float* srow = wstage + buf * ROW_FLOATS;

        // before overwriting this buffer, ensure TMA finished READING it
        if (ri >= 2) {
            if (lane == 0)
                asm volatile("cp.async.bulk.wait_group.read 1;" ::: "memory");
        }
        __syncwarp();

        const int yy = y - 2;
        const int g  = (yy >= 0) ? (yy >> 2) : -1;
        const int k  = yy - 4 * g;
        const float fy = 0.125f + 0.25f * (float)k;

        const float* row0 = &sS[(min(max(g, 0), H_ - 1) - R0) * 160];
        const float* row1 = &sS[(min(g + 1,     H_ - 1) - R0) * 160];

        #pragma unroll
        for (int j = 0; j < 5; j++) {
            const int c  = 32 * j + lane;
            const int cm = max(c - 1, 0);
            const int cp = min(c + 1, W_ - 1);

            const float a0 = row0[cm], a1 = row0[c], a2 = row0[cp];
            const float b0 = row1[cm], b1 = row1[c], b2 = row1[cp];
            const float v0 = fmaf(fy, b0 - a0, a0);
            const float v1 = fmaf(fy, b1 - a1, a1);
            const float v2 = fmaf(fy, b2 - a2, a2);
            const float da = v1 - v0;
            const float db = v2 - v1;

            float4 o;
            o.x = (fmaf(0.625f, da, v0) > 0.5f) ? 1.0f : 0.0f;
            o.y = (fmaf(0.875f, da, v0) > 0.5f) ? 1.0f : 0.0f;
            o.z = (fmaf(0.125f, db, v1) > 0.5f) ? 1.0f : 0.0f;
            o.w = (fmaf(0.375f, db, v1) > 0.5f) ? 1.0f : 0.0f;
            *reinterpret_cast<float4*>(srow + 4 * c) = o;
        }

        // make STS visible to the async proxy, then one lane issues the copy
        asm volatile("fence.proxy.async.shared::cta;" ::: "memory");
        __syncwarp();
        if (lane == 0) {
            const uint32_t s32 = (uint32_t)__cvta_generic_to_shared(srow);
            asm volatile("cp.async.bulk.global.shared::cta.bulk_group [%0], [%1], %2;"
                         :: "l"(gbase + (size_t)y * (OW_ * 4)),
                            "r"(s32), "r"((uint32_t)(ROW_FLOATS * 4))
                         : "memory");
            asm volatile("cp.async.bulk.commit_group;" ::: "memory");
        }
    }

    // full completion before kernel end
    if (lane == 0)
        asm volatile("cp.async.bulk.wait_group 0;" ::: "memory");
}

// ---------------------------------------------------------------------------
extern "C" void kernel_launch(void* const* d_in, const int* in_sizes, int n_in,
                              void* d_out, int out_size)
{
    // Size-based binding (robust to order/units): det << mc < proto
    const float* mc    = nullptr;
    const float* proto = nullptr;
    const void*  det   = nullptr;

    for (int i = 0; i < n_in; i++) {
        const long long s = in_sizes[i];
        if      (s == 1075200LL || s == 4300800LL)                        mc    = (const float*)d_in[i];
        else if (s == 3276800LL || s == 13107200LL)                       proto = (const float*)d_in[i];
        else if (s == 400LL || s == 800LL || s == 1600LL || s == 3200LL)  det   = d_in[i];
    }
    if (!mc || !proto || !det) {
        int imin = 0, imax = 0;
        for (int i = 1; i < 3 && i < n_in; i++) {
            if (in_sizes[i] < in_sizes[imin]) imin = i;
            if (in_sizes[i] > in_sizes[imax]) imax = i;
        }
        const int imid = 3 - imin - imax;
        det   = d_in[imin];
        proto = (const float*)d_in[imax];
        mc    = (const float*)d_in[imid];
    }

    float* out = (float*)d_out;     // [4,100,640,640] f32 (0.0/1.0)
    (void)out_size;

    cudaFuncSetAttribute(kernelB, cudaFuncAttributeMaxDynamicSharedMemorySize, SMEMB_BYTES);

    // d-half pipeline with HIGH-PRIORITY B stream:
    //   A1 -> evA1 ; A2 -> evA2   (default stream)
    //   s(hi): wait evA1 -> B1 ; wait evA2 -> B2
    // Priority lets B1's CTAs win work-distributor slots over A2's queued
    // blocks (R12's failure mode). Objects created fresh each call;
    // intentionally not destroyed (destroy mid-capture is illegal; harness
    // calls this only a few times).
    int prLo = 0, prHi = 0;
    cudaDeviceGetStreamPriorityRange(&prLo, &prHi);      // prHi = highest
    cudaStream_t s;
    cudaStreamCreateWithPriority(&s, cudaStreamNonBlocking, prHi);

    cudaEvent_t evA1, evA2, evB;
    cudaEventCreateWithFlags(&evA1, cudaEventDisableTiming);
    cudaEventCreateWithFlags(&evA2, cudaEventDisableTiming);
    cudaEventCreateWithFlags(&evB,  cudaEventDisableTiming);

    kernelA<<<dim3(HW_ / (256 * PXT_), 5, B_), 256>>>(mc, proto, det, 0);
    cudaEventRecord(evA1, 0);
    kernelA<<<dim3(HW_ / (256 * PXT_), 5, B_), 256>>>(mc, proto, det, 50);
    cudaEventRecord(evA2, 0);

    cudaStreamWaitEvent(s, evA1, 0);
    kernelB<<<dim3(8, 50, B_), 256, SMEMB_BYTES, s>>>(out, 0);
    cudaStreamWaitEvent(s, evA2, 0);
    kernelB<<<dim3(8, 50, B_), 256, SMEMB_BYTES, s>>>(out, 50);

    cudaEventRecord(evB, s);
    cudaStreamWaitEvent(0, evB, 0);
}

// round 16
// speedup vs baseline: 1.0448x; 1.0448x over previous
#include <cuda_runtime.h>
#include <math.h>
#include <stdint.h>

// Problem constants
#define B_   4
#define N_   8400
#define NM_  32
#define H_   160
#define W_   160
#define D_   100
#define HW_  (H_*W_)          // 25600
#define OW_  640
#define OH_  640

// Scratch: sigmoid masks [B][D][H][W] fp32 = 40.96 MB
__device__ float g_S[(size_t)B_ * D_ * HW_];

// Packed fp32x2 FMA (Blackwell FFMA2) — PTX-only
__device__ __forceinline__ float2 ffma2(float2 a, float2 b, float2 c) {
    union { float2 f; unsigned long long u; } ua, ub, uc, ur;
    ua.f = a; ub.f = b; uc.f = c;
    asm("fma.rn.f32x2 %0, %1, %2, %3;" : "=l"(ur.u) : "l"(ua.u), "l"(ub.u), "l"(uc.u));
    return ur.f;
}

// ---------------------------------------------------------------------------
// Kernel A (R8 design, best measured 28.4us; __expf sigmoid):
// coeff gather + GEMM over NM=32 + sigmoid -> g_S.
// grid (25, 10, 4); block 256; 3 CTAs/SM. Thread: 4 adjacent px x 10 d.
// ---------------------------------------------------------------------------
#define DT_  10
#define PXT_ 4

__global__ void __launch_bounds__(256, 3)
kernelA(const float* __restrict__ mc,
        const float* __restrict__ proto,
        const void* __restrict__ det)      // int32 vs int64 detected on device
{
    const int b  = blockIdx.z;
    const int d0 = blockIdx.y * DT_;
    const int p0 = blockIdx.x * (256 * PXT_) + threadIdx.x * PXT_;

    // int64 det values < 2^31 -> all odd int32 words zero
    const int* d32 = (const int*)det;
    bool is64 = true;
    #pragma unroll
    for (int k = 0; k < 8; k++) if (d32[2 * k + 1] != 0) is64 = false;

    __shared__ float sc[NM_][DT_];
    for (int i = threadIdx.x; i < NM_ * DT_; i += 256) {
        const int n = i / DT_;
        const int d = i % DT_;
        const int flat = b * D_ + d0 + d;
        long long idx = is64 ? ((const long long*)det)[flat] : (long long)d32[flat];
        idx = min(max(idx, 0LL), (long long)(N_ - 1));
        sc[n][d] = mc[((long long)b * N_ + idx) * NM_ + n];
    }
    __syncthreads();

    float2 acc[DT_][2];
    #pragma unroll
    for (int d = 0; d < DT_; d++) {
        acc[d][0] = make_float2(0.f, 0.f);
        acc[d][1] = make_float2(0.f, 0.f);
    }

    const float* pbase = proto + (size_t)b * NM_ * HW_ + p0;

    #pragma unroll 8
    for (int n = 0; n < NM_; n++) {
        const float4 p = *reinterpret_cast<const float4*>(pbase + (size_t)n * HW_);
        const float2 pa = make_float2(p.x, p.y);
        const float2 pb = make_float2(p.z, p.w);
        #pragma unroll
        for (int d = 0; d < DT_; d++) {
            const float c = sc[n][d];
            const float2 cc = make_float2(c, c);
            acc[d][0] = ffma2(pa, cc, acc[d][0]);
            acc[d][1] = ffma2(pb, cc, acc[d][1]);
        }
    }

    #pragma unroll
    for (int d = 0; d < DT_; d++) {
        float4 s;
        s.x = 1.0f / (1.0f + __expf(-acc[d][0].x));
        s.y = 1.0f / (1.0f + __expf(-acc[d][0].y));
        s.z = 1.0f / (1.0f + __expf(-acc[d][1].x));
        s.w = 1.0f / (1.0f + __expf(-acc[d][1].y));
        *reinterpret_cast<float4*>(g_S + ((size_t)(b * D_ + d0 + d)) * HW_ + p0) = s;
    }
}

// ---------------------------------------------------------------------------
// Kernel B (R9/R14 design — best measured, 104.8us): 4x bilinear upsample +
// threshold; per-warp row pipelines, per-row TMA bulk stores (double-
// buffered, wait_group.read 1).
// grid (8 bands, 100 d, 4 b); block 256 (8 warps); smem 55 KB -> 4 CTAs/SM.
// ---------------------------------------------------------------------------
#define SRCROWS      22                                  // 20 + 2 halo
#define BAND_FLOATS  (SRCROWS * 160)                     // 3520 floats
#define ROW_FLOATS   OW_                                 // 640 floats = 2560 B
#define SMEMB_BYTES  ((BAND_FLOATS + 8 * 2 * ROW_FLOATS) * 4)   // 55040 B

__global__ void __launch_bounds__(256)
kernelB(float* __restrict__ out)
{
    extern __shared__ float smem[];
    float* sS = smem;                                    // [22][160] band

    const int band = blockIdx.x;                         // 0..7
    const int d    = blockIdx.y;
    const int b    = blockIdx.z;
    const int R0   = 20 * band - 1;                      // first band source row
    const int Y0   = 80 * band;

    // load source band (smem row r holds global row clamp(R0 + r))
    const float* Sg = g_S + ((size_t)(b * D_ + d)) * HW_;
    for (int i = threadIdx.x; i < SRCROWS * 40; i += 256) {
        const int r  = i / 40;
        const int x4 = i % 40;
        const int gr = min(max(R0 + r, 0), H_ - 1);
        *reinterpret_cast<float4*>(&sS[r * 160 + x4 * 4]) =
            *reinterpret_cast<const float4*>(Sg + gr * 160 + x4 * 4);
    }
    __syncthreads();

    const int w    = threadIdx.x >> 5;
    const int lane = threadIdx.x & 31;
    float* wstage = smem + BAND_FLOATS + w * (2 * ROW_FLOATS);
    const char* gbase = (const char*)(out + ((size_t)(b * D_ + d)) * (OH_ * OW_));

    for (int ri = 0; ri < 10; ri++) {
        const int y   = Y0 + w + 8 * ri;
        const int buf = ri & 1;
        float* srow = wstage + buf * ROW_FLOATS;

        // before overwriting this buffer, ensure TMA finished READING it
        if (ri >= 2) {
            if (lane == 0)
                asm volatile("cp.async.bulk.wait_group.read 1;" ::: "memory");
        }
        __syncwarp();

        const int yy = y - 2;
        const int g  = (yy >= 0) ? (yy >> 2) : -1;
        const int k  = yy - 4 * g;
        const float fy = 0.125f + 0.25f * (float)k;

        const float* row0 = &sS[(min(max(g, 0), H_ - 1) - R0) * 160];
        const float* row1 = &sS[(min(g + 1,     H_ - 1) - R0) * 160];

        #pragma unroll
        for (int j = 0; j < 5; j++) {
            const int c  = 32 * j + lane;
            const int cm = max(c - 1, 0);
            const int cp = min(c + 1, W_ - 1);

            const float a0 = row0[cm], a1 = row0[c], a2 = row0[cp];
            const float b0 = row1[cm], b1 = row1[c], b2 = row1[cp];
            const float v0 = fmaf(fy, b0 - a0, a0);
            const float v1 = fmaf(fy, b1 - a1, a1);
            const float v2 = fmaf(fy, b2 - a2, a2);
            const float da = v1 - v0;
            const float db = v2 - v1;

            float4 o;
            o.x = (fmaf(0.625f, da, v0) > 0.5f) ? 1.0f : 0.0f;
            o.y = (fmaf(0.875f, da, v0) > 0.5f) ? 1.0f : 0.0f;
            o.z = (fmaf(0.125f, db, v1) > 0.5f) ? 1.0f : 0.0f;
            o.w = (fmaf(0.375f, db, v1) > 0.5f) ? 1.0f : 0.0f;
            *reinterpret_cast<float4*>(srow + 4 * c) = o;
        }

        // make STS visible to the async proxy, then one lane issues the copy
        asm volatile("fence.proxy.async.shared::cta;" ::: "memory");
        __syncwarp();
        if (lane == 0) {
            const uint32_t s32 = (uint32_t)__cvta_generic_to_shared(srow);
            asm volatile("cp.async.bulk.global.shared::cta.bulk_group [%0], [%1], %2;"
                         :: "l"(gbase + (size_t)y * (OW_ * 4)),
                            "r"(s32), "r"((uint32_t)(ROW_FLOATS * 4))
                         : "memory");
            asm volatile("cp.async.bulk.commit_group;" ::: "memory");
        }
    }

    // full completion before kernel end
    if (lane == 0)
        asm volatile("cp.async.bulk.wait_group 0;" ::: "memory");
}

// ---------------------------------------------------------------------------
extern "C" void kernel_launch(void* const* d_in, const int* in_sizes, int n_in,
                              void* d_out, int out_size)
{
    // Size-based binding (robust to order/units): det << mc < proto
    const float* mc    = nullptr;
    const float* proto = nullptr;
    const void*  det   = nullptr;

    for (int i = 0; i < n_in; i++) {
        const long long s = in_sizes[i];
        if      (s == 1075200LL || s == 4300800LL)                        mc    = (const float*)d_in[i];
        else if (s == 3276800LL || s == 13107200LL)                       proto = (const float*)d_in[i];
        else if (s == 400LL || s == 800LL || s == 1600LL || s == 3200LL)  det   = d_in[i];
    }
    if (!mc || !proto || !det) {
        int imin = 0, imax = 0;
        for (int i = 1; i < 3 && i < n_in; i++) {
            if (in_sizes[i] < in_sizes[imin]) imin = i;
            if (in_sizes[i] > in_sizes[imax]) imax = i;
        }
        const int imid = 3 - imin - imax;
        det   = d_in[imin];
        proto = (const float*)d_in[imax];
        mc    = (const float*)d_in[imid];
    }

    float* out = (float*)d_out;     // [4,100,640,640] f32 (0.0/1.0)
    (void)out_size;

    cudaFuncSetAttribute(kernelB, cudaFuncAttributeMaxDynamicSharedMemorySize, SMEMB_BYTES);

    // Serial, single stream: best-measured A then best-measured B.
    kernelA<<<dim3(HW_ / (256 * PXT_), D_ / DT_, B_), 256>>>(mc, proto, det);
    kernelB<<<dim3(8, D_, B_), 256, SMEMB_BYTES>>>(out);
}

// round 17
// speedup vs baseline: 1.0483x; 1.0033x over previous
#include <cuda_runtime.h>
#include <math.h>
#include <stdint.h>

// Problem constants
#define B_   4
#define N_   8400
#define NM_  32
#define H_   160
#define W_   160
#define D_   100
#define HW_  (H_*W_)          // 25600
#define OW_  640
#define OH_  640

// Scratch: sigmoid masks [B][D][H][W] fp32 = 40.96 MB
__device__ float g_S[(size_t)B_ * D_ * HW_];

// Packed fp32x2 FMA (Blackwell FFMA2) — PTX-only
__device__ __forceinline__ float2 ffma2(float2 a, float2 b, float2 c) {
    union { float2 f; unsigned long long u; } ua, ub, uc, ur;
    ua.f = a; ub.f = b; uc.f = c;
    asm("fma.rn.f32x2 %0, %1, %2, %3;" : "=l"(ur.u) : "l"(ua.u), "l"(ub.u), "l"(uc.u));
    return ur.f;
}

// ---------------------------------------------------------------------------
// Kernel A: coeff gather + GEMM over NM=32 + sigmoid -> g_S.
// grid (25, 10, 4); block 256; 3 CTAs/SM. Thread: 4 adjacent px x 10 d.
// Coeff rows padded to 12 floats (48 B, 16-aligned) so each n-iteration
// loads coefficients with LDS.128 x2 + LDS.64 instead of 10 scalar LDS.
// ---------------------------------------------------------------------------
#define DT_   10
#define DTP_  12
#define PXT_  4

__global__ void __launch_bounds__(256, 3)
kernelA(const float* __restrict__ mc,
        const float* __restrict__ proto,
        const void* __restrict__ det)      // int32 vs int64 detected on device
{
    const int b  = blockIdx.z;
    const int d0 = blockIdx.y * DT_;
    const int p0 = blockIdx.x * (256 * PXT_) + threadIdx.x * PXT_;

    // int64 det values < 2^31 -> all odd int32 words zero
    const int* d32 = (const int*)det;
    bool is64 = true;
    #pragma unroll
    for (int k = 0; k < 8; k++) if (d32[2 * k + 1] != 0) is64 = false;

    __shared__ float sc[NM_][DTP_];        // rows 48 B -> 16-B aligned
    for (int i = threadIdx.x; i < NM_ * DT_; i += 256) {
        const int n = i / DT_;
        const int d = i % DT_;
        const int flat = b * D_ + d0 + d;
        long long idx = is64 ? ((const long long*)det)[flat] : (long long)d32[flat];
        idx = min(max(idx, 0LL), (long long)(N_ - 1));
        sc[n][d] = mc[((long long)b * N_ + idx) * NM_ + n];
    }
    __syncthreads();

    float2 acc[DT_][2];
    #pragma unroll
    for (int d = 0; d < DT_; d++) {
        acc[d][0] = make_float2(0.f, 0.f);
        acc[d][1] = make_float2(0.f, 0.f);
    }

    const float* pbase = proto + (size_t)b * NM_ * HW_ + p0;

    #pragma unroll 8
    for (int n = 0; n < NM_; n++) {
        const float4 p = *reinterpret_cast<const float4*>(pbase + (size_t)n * HW_);
        const float2 pa = make_float2(p.x, p.y);
        const float2 pb = make_float2(p.z, p.w);

        // vectorized coefficient fetch: 2x LDS.128 + 1x LDS.64
        const float4 c0 = *reinterpret_cast<const float4*>(&sc[n][0]);
        const float4 c1 = *reinterpret_cast<const float4*>(&sc[n][4]);
        const float2 c2 = *reinterpret_cast<const float2*>(&sc[n][8]);
        const float cs[DT_] = {c0.x, c0.y, c0.z, c0.w,
                               c1.x, c1.y, c1.z, c1.w,
                               c2.x, c2.y};

        #pragma unroll
        for (int d = 0; d < DT_; d++) {
            const float2 cc = make_float2(cs[d], cs[d]);
            acc[d][0] = ffma2(pa, cc, acc[d][0]);
            acc[d][1] = ffma2(pb, cc, acc[d][1]);
        }
    }

    #pragma unroll
    for (int d = 0; d < DT_; d++) {
        float4 s;
        s.x = 1.0f / (1.0f + __expf(-acc[d][0].x));
        s.y = 1.0f / (1.0f + __expf(-acc[d][0].y));
        s.z = 1.0f / (1.0f + __expf(-acc[d][1].x));
        s.w = 1.0f / (1.0f + __expf(-acc[d][1].y));
        *reinterpret_cast<float4*>(g_S + ((size_t)(b * D_ + d0 + d)) * HW_ + p0) = s;
    }
}

// ---------------------------------------------------------------------------
// Kernel B (R9/R14 design — at its write floor, 106us): 4x bilinear upsample
// + threshold; per-warp row pipelines, per-row TMA bulk stores (double-
// buffered, wait_group.read 1).
// grid (8 bands, 100 d, 4 b); block 256 (8 warps); smem 55 KB -> 4 CTAs/SM.
// ---------------------------------------------------------------------------
#define SRCROWS      22                                  // 20 + 2 halo
#define BAND_FLOATS  (SRCROWS * 160)                     // 3520 floats
#define ROW_FLOATS   OW_                                 // 640 floats = 2560 B
#define SMEMB_BYTES  ((BAND_FLOATS + 8 * 2 * ROW_FLOATS) * 4)   // 55040 B

__global__ void __launch_bounds__(256)
kernelB(float* __restrict__ out)
{
    extern __shared__ float smem[];
    float* sS = smem;                                    // [22][160] band

    const int band = blockIdx.x;                         // 0..7
    const int d    = blockIdx.y;
    const int b    = blockIdx.z;
    const int R0   = 20 * band - 1;                      // first band source row
    const int Y0   = 80 * band;

    // load source band (smem row r holds global row clamp(R0 + r))
    const float* Sg = g_S + ((size_t)(b * D_ + d)) * HW_;
    for (int i = threadIdx.x; i < SRCROWS * 40; i += 256) {
        const int r  = i / 40;
        const int x4 = i % 40;
        const int gr = min(max(R0 + r, 0), H_ - 1);
        *reinterpret_cast<float4*>(&sS[r * 160 + x4 * 4]) =
            *reinterpret_cast<const float4*>(Sg + gr * 160 + x4 * 4);
    }
    __syncthreads();

    const int w    = threadIdx.x >> 5;
    const int lane = threadIdx.x & 31;
    float* wstage = smem + BAND_FLOATS + w * (2 * ROW_FLOATS);
    const char* gbase = (const char*)(out + ((size_t)(b * D_ + d)) * (OH_ * OW_));

    for (int ri = 0; ri < 10; ri++) {
        const int y   = Y0 + w + 8 * ri;
        const int buf = ri & 1;
        float* srow = wstage + buf * ROW_FLOATS;

        // before overwriting this buffer, ensure TMA finished READING it
        if (ri >= 2) {
            if (lane == 0)
                asm volatile("cp.async.bulk.wait_group.read 1;" ::: "memory");
        }
        __syncwarp();

        const int yy = y - 2;
        const int g  = (yy >= 0) ? (yy >> 2) : -1;
        const int k  = yy - 4 * g;
        const float fy = 0.125f + 0.25f * (float)k;

        const float* row0 = &sS[(min(max(g, 0), H_ - 1) - R0) * 160];
        const float* row1 = &sS[(min(g + 1,     H_ - 1) - R0) * 160];

        #pragma unroll
        for (int j = 0; j < 5; j++) {
            const int c  = 32 * j + lane;
            const int cm = max(c - 1, 0);
            const int cp = min(c + 1, W_ - 1);

            const float a0 = row0[cm], a1 = row0[c], a2 = row0[cp];
            const float b0 = row1[cm], b1 = row1[c], b2 = row1[cp];
            const float v0 = fmaf(fy, b0 - a0, a0);
            const float v1 = fmaf(fy, b1 - a1, a1);
            const float v2 = fmaf(fy, b2 - a2, a2);
            const float da = v1 - v0;
            const float db = v2 - v1;

            float4 o;
            o.x = (fmaf(0.625f, da, v0) > 0.5f) ? 1.0f : 0.0f;
            o.y = (fmaf(0.875f, da, v0) > 0.5f) ? 1.0f : 0.0f;
            o.z = (fmaf(0.125f, db, v1) > 0.5f) ? 1.0f : 0.0f;
            o.w = (fmaf(0.375f, db, v1) > 0.5f) ? 1.0f : 0.0f;
            *reinterpret_cast<float4*>(srow + 4 * c) = o;
        }

        // make STS visible to the async proxy, then one lane issues the copy
        asm volatile("fence.proxy.async.shared::cta;" ::: "memory");
        __syncwarp();
        if (lane == 0) {
            const uint32_t s32 = (uint32_t)__cvta_generic_to_shared(srow);
            asm volatile("cp.async.bulk.global.shared::cta.bulk_group [%0], [%1], %2;"
                         :: "l"(gbase + (size_t)y * (OW_ * 4)),
                            "r"(s32), "r"((uint32_t)(ROW_FLOATS * 4))
                         : "memory");
            asm volatile("cp.async.bulk.commit_group;" ::: "memory");
        }
    }

    // full completion before kernel end
    if (lane == 0)
        asm volatile("cp.async.bulk.wait_group 0;" ::: "memory");
}

// ---------------------------------------------------------------------------
extern "C" void kernel_launch(void* const* d_in, const int* in_sizes, int n_in,
                              void* d_out, int out_size)
{
    // Size-based binding (robust to order/units): det << mc < proto
    const float* mc    = nullptr;
    const float* proto = nullptr;
    const void*  det   = nullptr;

    for (int i = 0; i < n_in; i++) {
        const long long s = in_sizes[i];
        if      (s == 1075200LL || s == 4300800LL)                        mc    = (const float*)d_in[i];
        else if (s == 3276800LL || s == 13107200LL)                       proto = (const float*)d_in[i];
        else if (s == 400LL || s == 800LL || s == 1600LL || s == 3200LL)  det   = d_in[i];
    }
    if (!mc || !proto || !det) {
        int imin = 0, imax = 0;
        for (int i = 1; i < 3 && i < n_in; i++) {
            if (in_sizes[i] < in_sizes[imin]) imin = i;
            if (in_sizes[i] > in_sizes[imax]) imax = i;
        }
        const int imid = 3 - imin - imax;
        det   = d_in[imin];
        proto = (const float*)d_in[imax];
        mc    = (const float*)d_in[imid];
    }

    float* out = (float*)d_out;     // [4,100,640,640] f32 (0.0/1.0)
    (void)out_size;

    cudaFuncSetAttribute(kernelB, cudaFuncAttributeMaxDynamicSharedMemorySize, SMEMB_BYTES);

    // Serial, single stream: A then B (B owns the write-path floor).
    kernelA<<<dim3(HW_ / (256 * PXT_), D_ / DT_, B_), 256>>>(mc, proto, det);
    kernelB<<<dim3(8, D_, B_), 256, SMEMB_BYTES>>>(out);
}